// round 7
// baseline (speedup 1.0000x reference)
#include <cuda_runtime.h>
#include <cuda_bf16.h>
#include <math.h>
#include <stdint.h>

// Problem constants (fixed by the reference)
#define INF   64
#define HID   128
#define LAT   32
#define HARM  8
#define NLAY  3
#define NG    64
#define NMAX  50000
#define EMAX  1600000

// ---------------- device scratch (no allocations allowed) ----------------
__device__ float g_bufA[NMAX * HID];
__device__ float g_bufB[NMAX * HID];
__device__ float g_dinv[NMAX];
__device__ int   g_deg[NMAX];
__device__ int   g_offs[NMAX + 1];
__device__ int   g_cursor[NMAX];
__device__ int   g_esrc[EMAX];
__device__ float g_wt_embed[INF * 16 * HID];          // [k=1024][o=128]
__device__ float g_wt_mp[NLAY][HID * 16 * HID];       // [k=2048][o=128]
__device__ float g_wt_read[HID * 16 * LAT];           // [k=2048][o=32]
__device__ float g_pool[NG * HID];
__device__ float g_cnt[NG];
__device__ float g_y[NG * HID];

// ---------------- packed f32x2 FMA (sm_100+) ----------------
__device__ __forceinline__ void fma2(unsigned long long& d, unsigned long long a,
                                     unsigned long long b) {
    asm("fma.rn.f32x2 %0, %1, %2, %0;" : "+l"(d) : "l"(a), "l"(b));
}

// ---------------- weight transpose: W[2,OUT,IN,H] -> Wt[k][OUT], k=(i*H+h)*2+s
__global__ void transpose_w(const float* __restrict__ W, float* __restrict__ Wt,
                            int OUT, int IN_F) {
    int idx = blockIdx.x * blockDim.x + threadIdx.x;
    int total = 2 * OUT * IN_F * HARM;
    if (idx >= total) return;
    int o = idx % OUT;
    int k = idx / OUT;
    int s = k & 1;
    int h = (k >> 1) & (HARM - 1);
    int i = k >> 4;
    Wt[idx] = W[(((size_t)s * OUT + o) * IN_F + i) * HARM + h];
}

// ---------------- degree histogram / scan / dinv / CSR placement ----------
__global__ void deg_kernel(const int* __restrict__ ei, int* __restrict__ deg, int E) {
    int e = blockIdx.x * blockDim.x + threadIdx.x;
    if (e < E) atomicAdd(&deg[ei[E + e]], 1);
}

__global__ void scan_kernel(const int* __restrict__ deg, int* __restrict__ offs,
                            int* __restrict__ cursor, int n) {
    __shared__ int sh_warp[32];
    __shared__ int sh_carry;
    const int tid = threadIdx.x, lane = tid & 31, w = tid >> 5;
    if (tid == 0) sh_carry = 0;
    __syncthreads();
    for (int base = 0; base < n; base += 1024) {
        int i = base + tid;
        int v = (i < n) ? deg[i] : 0;
        int x = v;
#pragma unroll
        for (int d = 1; d < 32; d <<= 1) {
            int y = __shfl_up_sync(0xffffffffu, x, d);
            if (lane >= d) x += y;
        }
        if (lane == 31) sh_warp[w] = x;
        __syncthreads();
        if (w == 0) {
            int s = sh_warp[lane];
#pragma unroll
            for (int d = 1; d < 32; d <<= 1) {
                int y = __shfl_up_sync(0xffffffffu, s, d);
                if (lane >= d) s += y;
            }
            sh_warp[lane] = s;
        }
        __syncthreads();
        int warp_off = (w == 0) ? 0 : sh_warp[w - 1];
        int excl = sh_carry + warp_off + x - v;
        if (i < n) { offs[i] = excl; cursor[i] = excl; }
        __syncthreads();
        if (tid == 0) sh_carry += sh_warp[31];
        __syncthreads();
    }
    if (threadIdx.x == 0) offs[n] = sh_carry;
}

__global__ void dinv_kernel(const int* __restrict__ deg, float* __restrict__ dinv, int n) {
    int i = blockIdx.x * blockDim.x + threadIdx.x;
    if (i < n) dinv[i] = rsqrtf((float)(deg[i] + 1));   // +1 = self loop
}

__global__ void place_kernel(const int* __restrict__ ei, int* __restrict__ cursor,
                             int* __restrict__ esrc, int E) {
    int e = blockIdx.x * blockDim.x + threadIdx.x;
    if (e >= E) return;
    int r = ei[e], c = ei[E + e];
    int p = atomicAdd(&cursor[c], 1);
    esrc[p] = r;
}

// ---------------- fused KAN GEMM via fma.rn.f32x2 ----------------
// Y[N,128] = Phi(X)[N, KF*16] @ Wt^T.  CTA tile 128x128, 256 threads,
// thread micro-tile 8x8 (stored as 8 rows x 4 packed col-pairs).
// A tile is stored DUPLICATED in smem: sh_phi2[k][2*row] = sh_phi2[k][2*row+1]
// so the scalar broadcast operand is a ready-made f32x2.
template <int KF>
__launch_bounds__(256)
__global__ void kan_gemm_f2(const float* __restrict__ X, const float* __restrict__ Wt,
                            float* __restrict__ Y, int n) {
    __shared__ __align__(16) float sh_phi2[16][256];   // 16 KB (dup A)
    __shared__ __align__(16) float sh_w[16][128];      // 8 KB

    const int tid = threadIdx.x;
    const int bm  = blockIdx.x * 128;
    const int tx  = tid & 15;
    const int ty  = tid >> 4;

    unsigned long long acc[8][4];
#pragma unroll
    for (int r = 0; r < 8; r++)
#pragma unroll
        for (int c = 0; c < 4; c++) acc[r][c] = 0ull;

    for (int i = 0; i < KF; i++) {
        if (tid < 128) {
            // produce Phi (dup pairs) for feature i, node row = tid
            int m = bm + tid;
            float x = (m < n) ? X[(size_t)m * KF + i] : 0.f;
            float s1, c1;
            sincosf(x, &s1, &c1);
            float cp = 1.f, sp = 0.f, cc = c1, sc = s1;
#pragma unroll
            for (int h = 0; h < HARM; h++) {
                *(float2*)&sh_phi2[2 * h][2 * tid]     = make_float2(cc, cc);
                *(float2*)&sh_phi2[2 * h + 1][2 * tid] = make_float2(sc, sc);
                float cn = 2.f * c1 * cc - cp;
                float sn = 2.f * c1 * sc - sp;
                cp = cc; sp = sc; cc = cn; sc = sn;
            }
        } else {
            // stage W tile [16][128] (coalesced float4)
            int t = tid - 128;
            const float4* src = (const float4*)(Wt + (size_t)i * 16 * HID);
            float4* dst = (float4*)(&sh_w[0][0]);
#pragma unroll
            for (int j = 0; j < 4; j++) dst[t + j * 128] = src[t + j * 128];
        }
        __syncthreads();

#pragma unroll
        for (int kk = 0; kk < 16; kk++) {
            const char* pa = (const char*)sh_phi2 + kk * 1024 + ty * 64;
            ulonglong2 a01 = *(const ulonglong2*)(pa);
            ulonglong2 a23 = *(const ulonglong2*)(pa + 16);
            ulonglong2 a45 = *(const ulonglong2*)(pa + 32);
            ulonglong2 a67 = *(const ulonglong2*)(pa + 48);
            const char* pb = (const char*)sh_w + kk * 512 + tx * 32;
            ulonglong2 b01 = *(const ulonglong2*)(pb);
            ulonglong2 b23 = *(const ulonglong2*)(pb + 16);
            unsigned long long a[8] = {a01.x, a01.y, a23.x, a23.y,
                                       a45.x, a45.y, a67.x, a67.y};
            unsigned long long b[4] = {b01.x, b01.y, b23.x, b23.y};
#pragma unroll
            for (int r = 0; r < 8; r++)
#pragma unroll
                for (int c = 0; c < 4; c++)
                    fma2(acc[r][c], a[r], b[c]);
        }
        __syncthreads();
    }

    // write out
#pragma unroll
    for (int r = 0; r < 8; r++) {
        int m = bm + ty * 8 + r;
        if (m < n) {
            float2 p0 = *(float2*)&acc[r][0];
            float2 p1 = *(float2*)&acc[r][1];
            float2 p2 = *(float2*)&acc[r][2];
            float2 p3 = *(float2*)&acc[r][3];
            float4* out = (float4*)(Y + (size_t)m * HID + tx * 8);
            out[0] = make_float4(p0.x, p0.y, p1.x, p1.y);
            out[1] = make_float4(p2.x, p2.y, p3.x, p3.y);
        }
    }
}

// ---------------- CSR gather aggregation (no atomics) ----------------
// dst[c] = dinv[c]^2 * src[c] + sum_{r in N(c)} dinv[r]*dinv[c]*src[r]
__global__ void gather_kernel(const float* __restrict__ src, float* __restrict__ dst,
                              const int* __restrict__ esrc, const int* __restrict__ offs,
                              const float* __restrict__ dinv, int n) {
    int gw   = (blockIdx.x * blockDim.x + threadIdx.x) >> 5;
    int lane = threadIdx.x & 31;
    if (gw >= n) return;
    const int c  = gw;
    const int s0 = offs[c];
    const int s1 = offs[c + 1];
    const float dc = dinv[c];

    float4 acc;
    {
        float4 v = ((const float4*)(src + (size_t)c * HID))[lane];
        float w = dc * dc;
        acc = make_float4(w * v.x, w * v.y, w * v.z, w * v.w);
    }

    for (int j = s0; j < s1; j += 32) {
        int cnt = min(32, s1 - j);
        int idx = (lane < cnt) ? esrc[j + lane] : 0;
        float w  = (lane < cnt) ? dinv[idx] : 0.f;
        int t = 0;
        for (; t + 2 <= cnt; t += 2) {
            int r0 = __shfl_sync(0xffffffffu, idx, t);
            int r1 = __shfl_sync(0xffffffffu, idx, t + 1);
            float w0 = __shfl_sync(0xffffffffu, w, t);
            float w1 = __shfl_sync(0xffffffffu, w, t + 1);
            float4 v0 = ((const float4*)(src + (size_t)r0 * HID))[lane];
            float4 v1 = ((const float4*)(src + (size_t)r1 * HID))[lane];
            float f0 = dc * w0, f1 = dc * w1;
            acc.x += f0 * v0.x + f1 * v1.x;
            acc.y += f0 * v0.y + f1 * v1.y;
            acc.z += f0 * v0.z + f1 * v1.z;
            acc.w += f0 * v0.w + f1 * v1.w;
        }
        if (t < cnt) {
            int r0 = __shfl_sync(0xffffffffu, idx, t);
            float w0 = __shfl_sync(0xffffffffu, w, t);
            float4 v0 = ((const float4*)(src + (size_t)r0 * HID))[lane];
            float f0 = dc * w0;
            acc.x += f0 * v0.x; acc.y += f0 * v0.y;
            acc.z += f0 * v0.z; acc.w += f0 * v0.w;
        }
    }
    ((float4*)(dst + (size_t)c * HID))[lane] = acc;
}

// ---------------- mean pool (batch sorted -> run-length flush) ----------
__global__ void pool_kernel(const float* __restrict__ h, const int* __restrict__ batch,
                            float* __restrict__ pool, float* __restrict__ cnt, int n) {
    int c  = threadIdx.x;         // 0..127
    int n0 = blockIdx.x * 256;
    if (n0 >= n) return;
    int nend = min(n0 + 256, n);
    float acc = 0.f;
    int cur = batch[n0];
    int runStart = n0;
    for (int m = n0; m < nend; m++) {
        int b = batch[m];
        if (b != cur) {
            atomicAdd(&pool[cur * HID + c], acc);
            if (c == 0) atomicAdd(&cnt[cur], (float)(m - runStart));
            acc = 0.f; cur = b; runStart = m;
        }
        acc += h[(size_t)m * HID + c];
    }
    atomicAdd(&pool[cur * HID + c], acc);
    if (c == 0) atomicAdd(&cnt[cur], (float)(nend - runStart));
}

__global__ void mean_kernel(const float* __restrict__ pool, const float* __restrict__ cnt,
                            float* __restrict__ y) {
    int idx = blockIdx.x * blockDim.x + threadIdx.x;
    if (idx >= NG * HID) return;
    int g = idx >> 7;
    y[idx] = pool[idx] / fmaxf(cnt[g], 1.0f);
}

// ---------------- readout KAN: [64,128] -> [64,32] -------------------------
__global__ void kan_read_kernel(const float* __restrict__ Y, const float* __restrict__ Wt,
                                float* __restrict__ out) {
    int idx = blockIdx.x * blockDim.x + threadIdx.x;
    if (idx >= NG * LAT) return;
    int g = idx >> 5;
    int o = idx & 31;
    float acc = 0.f;
    for (int i = 0; i < HID; i++) {
        float x = Y[g * HID + i];
        float s1, c1;
        sincosf(x, &s1, &c1);
        float cp = 1.f, sp = 0.f, cc = c1, sc = s1;
#pragma unroll
        for (int h = 0; h < HARM; h++) {
            const float* w = Wt + ((size_t)(i * HARM + h) * 2) * LAT;
            acc = fmaf(cc, w[o], acc);
            acc = fmaf(sc, w[LAT + o], acc);
            float cn = 2.f * c1 * cc - cp;
            float sn = 2.f * c1 * sc - sp;
            cp = cc; sp = sc; cc = cn; sc = sn;
        }
    }
    out[idx] = acc;
}

// ---------------- launch ----------------------------------------------------
extern "C" void kernel_launch(void* const* d_in, const int* in_sizes, int n_in,
                              void* d_out, int out_size) {
    const float* features = (const float*)d_in[0];
    const int*   ei       = (const int*)d_in[1];
    const int*   batch    = (const int*)d_in[2];
    const float* W_embed  = (const float*)d_in[3];
    const float* W_mp     = (const float*)d_in[4];
    const float* W_read   = (const float*)d_in[5];
    float*       out      = (float*)d_out;

    const int n = in_sizes[0] / INF;
    const int E = in_sizes[1] / 2;

    float *p_bufA, *p_bufB, *p_dinv, *p_pool, *p_cnt, *p_y;
    float *p_wte, *p_wtm, *p_wtr;
    int   *p_deg, *p_offs, *p_cursor, *p_esrc;
    cudaGetSymbolAddress((void**)&p_bufA,   g_bufA);
    cudaGetSymbolAddress((void**)&p_bufB,   g_bufB);
    cudaGetSymbolAddress((void**)&p_dinv,   g_dinv);
    cudaGetSymbolAddress((void**)&p_deg,    g_deg);
    cudaGetSymbolAddress((void**)&p_offs,   g_offs);
    cudaGetSymbolAddress((void**)&p_cursor, g_cursor);
    cudaGetSymbolAddress((void**)&p_esrc,   g_esrc);
    cudaGetSymbolAddress((void**)&p_wte,    g_wt_embed);
    cudaGetSymbolAddress((void**)&p_wtm,    g_wt_mp);
    cudaGetSymbolAddress((void**)&p_wtr,    g_wt_read);
    cudaGetSymbolAddress((void**)&p_pool,   g_pool);
    cudaGetSymbolAddress((void**)&p_cnt,    g_cnt);
    cudaGetSymbolAddress((void**)&p_y,      g_y);

    const int gblocks = (n + 127) / 128;
    const int wtot_mp = HID * 16 * HID;     // 2048 * 128

    // -- embedding path first (so ncu -s 5 lands on a GEMM, not prep) --
    transpose_w<<<(INF * 16 * HID + 255) / 256, 256>>>(W_embed, p_wte, HID, INF);
    kan_gemm_f2<INF><<<gblocks, 256>>>(features, p_wte, p_bufA, n);

    transpose_w<<<(wtot_mp + 255) / 256, 256>>>(W_mp, p_wtm, HID, HID);
    kan_gemm_f2<HID><<<gblocks, 256>>>(p_bufA, p_wtm, p_bufB, n);

    // -- CSR build --
    cudaMemsetAsync(p_deg, 0, (size_t)n * sizeof(int));
    deg_kernel<<<(E + 255) / 256, 256>>>(ei, p_deg, E);
    scan_kernel<<<1, 1024>>>(p_deg, p_offs, p_cursor, n);
    dinv_kernel<<<(n + 255) / 256, 256>>>(p_deg, p_dinv, n);
    place_kernel<<<(E + 255) / 256, 256>>>(ei, p_cursor, p_esrc, E);

    // layer 0 aggregation
    gather_kernel<<<(n * 32 + 255) / 256, 256>>>(p_bufB, p_bufA, p_esrc, p_offs, p_dinv, n);

    // layers 1..2
    for (int l = 1; l < NLAY; l++) {
        transpose_w<<<(wtot_mp + 255) / 256, 256>>>(W_mp + (size_t)l * wtot_mp,
                                                    p_wtm + (size_t)l * wtot_mp, HID, HID);
        kan_gemm_f2<HID><<<gblocks, 256>>>(p_bufA, p_wtm + (size_t)l * wtot_mp, p_bufB, n);
        gather_kernel<<<(n * 32 + 255) / 256, 256>>>(p_bufB, p_bufA, p_esrc, p_offs, p_dinv, n);
    }

    // -- mean pool + readout --
    transpose_w<<<(2 * LAT * HID * HARM + 255) / 256, 256>>>(W_read, p_wtr, LAT, HID);
    cudaMemsetAsync(p_pool, 0, NG * HID * sizeof(float));
    cudaMemsetAsync(p_cnt,  0, NG * sizeof(float));
    pool_kernel<<<(n + 255) / 256, 128>>>(p_bufA, batch, p_pool, p_cnt, n);
    mean_kernel<<<(NG * HID + 255) / 256, 256>>>(p_pool, p_cnt, p_y);
    kan_read_kernel<<<(NG * LAT + 255) / 256, 256>>>(p_y, p_wtr, out);
}

// round 8
// speedup vs baseline: 1.9048x; 1.9048x over previous
#include <cuda_runtime.h>
#include <cuda_bf16.h>
#include <math.h>
#include <stdint.h>

// Problem constants (fixed by the reference)
#define INF   64
#define HID   128
#define LAT   32
#define HARM  8
#define NLAY  3
#define NG    64
#define NMAX  50000
#define EMAX  1600000

// ---------------- device scratch (no allocations allowed) ----------------
__device__ float g_bufA[NMAX * HID];
__device__ float g_bufB[NMAX * HID];
__device__ float g_dinv[NMAX];
__device__ int   g_deg[NMAX];
__device__ int   g_offs[NMAX + 1];
__device__ int   g_cursor[NMAX];
__device__ int   g_esrc[EMAX];
__device__ float g_wt_embed[INF * 16 * HID];          // [k=1024][o=128]
__device__ float g_wt_mp[NLAY][HID * 16 * HID];       // [k=2048][o=128]
__device__ float g_wt_read[HID * 16 * LAT];           // [k=2048][o=32]
__device__ float g_pool[NG * HID];
__device__ float g_cnt[NG];
__device__ float g_y[NG * HID];

// ---------------- weight transpose: W[2,OUT,IN,H] -> Wt[k][OUT], k=(i*H+h)*2+s
__global__ void transpose_w(const float* __restrict__ W, float* __restrict__ Wt,
                            int OUT, int IN_F) {
    int idx = blockIdx.x * blockDim.x + threadIdx.x;
    int total = 2 * OUT * IN_F * HARM;
    if (idx >= total) return;
    int o = idx % OUT;
    int k = idx / OUT;
    int s = k & 1;
    int h = (k >> 1) & (HARM - 1);
    int i = k >> 4;
    Wt[idx] = W[(((size_t)s * OUT + o) * IN_F + i) * HARM + h];
}

// ---------------- degree histogram / scan / dinv / CSR placement ----------
__global__ void deg_kernel(const int* __restrict__ ei, int* __restrict__ deg, int E) {
    int e = blockIdx.x * blockDim.x + threadIdx.x;
    if (e < E) atomicAdd(&deg[ei[E + e]], 1);
}

__global__ void scan_kernel(const int* __restrict__ deg, int* __restrict__ offs,
                            int* __restrict__ cursor, int n) {
    __shared__ int sh_warp[32];
    __shared__ int sh_carry;
    const int tid = threadIdx.x, lane = tid & 31, w = tid >> 5;
    if (tid == 0) sh_carry = 0;
    __syncthreads();
    for (int base = 0; base < n; base += 1024) {
        int i = base + tid;
        int v = (i < n) ? deg[i] : 0;
        int x = v;
#pragma unroll
        for (int d = 1; d < 32; d <<= 1) {
            int y = __shfl_up_sync(0xffffffffu, x, d);
            if (lane >= d) x += y;
        }
        if (lane == 31) sh_warp[w] = x;
        __syncthreads();
        if (w == 0) {
            int s = sh_warp[lane];
#pragma unroll
            for (int d = 1; d < 32; d <<= 1) {
                int y = __shfl_up_sync(0xffffffffu, s, d);
                if (lane >= d) s += y;
            }
            sh_warp[lane] = s;
        }
        __syncthreads();
        int warp_off = (w == 0) ? 0 : sh_warp[w - 1];
        int excl = sh_carry + warp_off + x - v;
        if (i < n) { offs[i] = excl; cursor[i] = excl; }
        __syncthreads();
        if (tid == 0) sh_carry += sh_warp[31];
        __syncthreads();
    }
    if (threadIdx.x == 0) offs[n] = sh_carry;
}

__global__ void dinv_kernel(const int* __restrict__ deg, float* __restrict__ dinv, int n) {
    int i = blockIdx.x * blockDim.x + threadIdx.x;
    if (i < n) dinv[i] = rsqrtf((float)(deg[i] + 1));   // +1 = self loop
}

__global__ void place_kernel(const int* __restrict__ ei, int* __restrict__ cursor,
                             int* __restrict__ esrc, int E) {
    int e = blockIdx.x * blockDim.x + threadIdx.x;
    if (e >= E) return;
    int r = ei[e], c = ei[E + e];
    int p = atomicAdd(&cursor[c], 1);
    esrc[p] = r;
}

// ---------------- fused KAN GEMM (scalar FFMA, proven R1 kernel) -----------
// Y[N,128] = Phi(X)[N, KF*16] @ Wt^T.  CTA 128x128, 256 threads, 8x8 micro.
template <int KF>
__launch_bounds__(256, 2)
__global__ void kan_gemm(const float* __restrict__ X, const float* __restrict__ Wt,
                         float* __restrict__ Y, int n) {
    __shared__ float sh_phi[16][HID];
    __shared__ float sh_w[16][HID];

    const int tid = threadIdx.x;
    const int bm  = blockIdx.x * 128;
    const int tx  = tid & 15;    // output col group
    const int ty  = tid >> 4;    // node row group

    float acc[8][8];
#pragma unroll
    for (int r = 0; r < 8; r++)
#pragma unroll
        for (int c = 0; c < 8; c++) acc[r][c] = 0.f;

    for (int i = 0; i < KF; i++) {
        if (tid < 128) {
            // produce Phi tile for feature i (one node per thread)
            int m = bm + tid;
            float x = (m < n) ? X[(size_t)m * KF + i] : 0.f;
            float s1, c1;
            sincosf(x, &s1, &c1);
            float cp = 1.f, sp = 0.f, cc = c1, sc = s1;
#pragma unroll
            for (int h = 0; h < HARM; h++) {
                sh_phi[2 * h][tid]     = cc;
                sh_phi[2 * h + 1][tid] = sc;
                float cn = 2.f * c1 * cc - cp;
                float sn = 2.f * c1 * sc - sp;
                cp = cc; sp = sc; cc = cn; sc = sn;
            }
        } else {
            // stage W tile [16][128] (coalesced float4)
            int t = tid - 128;
            const float4* src = (const float4*)(Wt + (size_t)i * 16 * HID);
            float4* dst = (float4*)(&sh_w[0][0]);
#pragma unroll
            for (int j = 0; j < 4; j++) dst[t + j * 128] = src[t + j * 128];
        }
        __syncthreads();

#pragma unroll
        for (int kk = 0; kk < 16; kk++) {
            float4 a0 = *(const float4*)(&sh_phi[kk][ty * 8]);
            float4 a1 = *(const float4*)(&sh_phi[kk][ty * 8 + 4]);
            float4 b0 = *(const float4*)(&sh_w[kk][tx * 8]);
            float4 b1 = *(const float4*)(&sh_w[kk][tx * 8 + 4]);
            float a[8] = {a0.x, a0.y, a0.z, a0.w, a1.x, a1.y, a1.z, a1.w};
            float b[8] = {b0.x, b0.y, b0.z, b0.w, b1.x, b1.y, b1.z, b1.w};
#pragma unroll
            for (int r = 0; r < 8; r++)
#pragma unroll
                for (int c = 0; c < 8; c++)
                    acc[r][c] = fmaf(a[r], b[c], acc[r][c]);
        }
        __syncthreads();
    }

    // write out
#pragma unroll
    for (int r = 0; r < 8; r++) {
        int m = bm + ty * 8 + r;
        if (m < n) {
            float4 v0 = make_float4(acc[r][0], acc[r][1], acc[r][2], acc[r][3]);
            float4 v1 = make_float4(acc[r][4], acc[r][5], acc[r][6], acc[r][7]);
            float4* out = (float4*)(Y + (size_t)m * HID + tx * 8);
            out[0] = v0;
            out[1] = v1;
        }
    }
}

// ---------------- CSR gather aggregation (no atomics) ----------------
// dst[c] = dinv[c]^2 * src[c] + sum_{r in N(c)} dinv[r]*dinv[c]*src[r]
__global__ void gather_kernel(const float* __restrict__ src, float* __restrict__ dst,
                              const int* __restrict__ esrc, const int* __restrict__ offs,
                              const float* __restrict__ dinv, int n) {
    int gw   = (blockIdx.x * blockDim.x + threadIdx.x) >> 5;
    int lane = threadIdx.x & 31;
    if (gw >= n) return;
    const int c  = gw;
    const int s0 = offs[c];
    const int s1 = offs[c + 1];
    const float dc = dinv[c];

    float4 acc;
    {
        float4 v = ((const float4*)(src + (size_t)c * HID))[lane];
        float w = dc * dc;
        acc = make_float4(w * v.x, w * v.y, w * v.z, w * v.w);
    }

    for (int j = s0; j < s1; j += 32) {
        int cnt = min(32, s1 - j);
        int idx = (lane < cnt) ? esrc[j + lane] : 0;
        float w  = (lane < cnt) ? dinv[idx] : 0.f;
        int t = 0;
        for (; t + 2 <= cnt; t += 2) {
            int r0 = __shfl_sync(0xffffffffu, idx, t);
            int r1 = __shfl_sync(0xffffffffu, idx, t + 1);
            float w0 = __shfl_sync(0xffffffffu, w, t);
            float w1 = __shfl_sync(0xffffffffu, w, t + 1);
            float4 v0 = ((const float4*)(src + (size_t)r0 * HID))[lane];
            float4 v1 = ((const float4*)(src + (size_t)r1 * HID))[lane];
            float f0 = dc * w0, f1 = dc * w1;
            acc.x += f0 * v0.x + f1 * v1.x;
            acc.y += f0 * v0.y + f1 * v1.y;
            acc.z += f0 * v0.z + f1 * v1.z;
            acc.w += f0 * v0.w + f1 * v1.w;
        }
        if (t < cnt) {
            int r0 = __shfl_sync(0xffffffffu, idx, t);
            float w0 = __shfl_sync(0xffffffffu, w, t);
            float4 v0 = ((const float4*)(src + (size_t)r0 * HID))[lane];
            float f0 = dc * w0;
            acc.x += f0 * v0.x; acc.y += f0 * v0.y;
            acc.z += f0 * v0.z; acc.w += f0 * v0.w;
        }
    }
    ((float4*)(dst + (size_t)c * HID))[lane] = acc;
}

// ---------------- mean pool (batch sorted -> run-length flush) ----------
__global__ void pool_kernel(const float* __restrict__ h, const int* __restrict__ batch,
                            float* __restrict__ pool, float* __restrict__ cnt, int n) {
    int c  = threadIdx.x;         // 0..127
    int n0 = blockIdx.x * 256;
    if (n0 >= n) return;
    int nend = min(n0 + 256, n);
    float acc = 0.f;
    int cur = batch[n0];
    int runStart = n0;
    for (int m = n0; m < nend; m++) {
        int b = batch[m];
        if (b != cur) {
            atomicAdd(&pool[cur * HID + c], acc);
            if (c == 0) atomicAdd(&cnt[cur], (float)(m - runStart));
            acc = 0.f; cur = b; runStart = m;
        }
        acc += h[(size_t)m * HID + c];
    }
    atomicAdd(&pool[cur * HID + c], acc);
    if (c == 0) atomicAdd(&cnt[cur], (float)(nend - runStart));
}

__global__ void mean_kernel(const float* __restrict__ pool, const float* __restrict__ cnt,
                            float* __restrict__ y) {
    int idx = blockIdx.x * blockDim.x + threadIdx.x;
    if (idx >= NG * HID) return;
    int g = idx >> 7;
    y[idx] = pool[idx] / fmaxf(cnt[g], 1.0f);
}

// ---------------- readout KAN: [64,128] -> [64,32] -------------------------
__global__ void kan_read_kernel(const float* __restrict__ Y, const float* __restrict__ Wt,
                                float* __restrict__ out) {
    int idx = blockIdx.x * blockDim.x + threadIdx.x;
    if (idx >= NG * LAT) return;
    int g = idx >> 5;
    int o = idx & 31;
    float acc = 0.f;
    for (int i = 0; i < HID; i++) {
        float x = Y[g * HID + i];
        float s1, c1;
        sincosf(x, &s1, &c1);
        float cp = 1.f, sp = 0.f, cc = c1, sc = s1;
#pragma unroll
        for (int h = 0; h < HARM; h++) {
            const float* w = Wt + ((size_t)(i * HARM + h) * 2) * LAT;
            acc = fmaf(cc, w[o], acc);
            acc = fmaf(sc, w[LAT + o], acc);
            float cn = 2.f * c1 * cc - cp;
            float sn = 2.f * c1 * sc - sp;
            cp = cc; sp = sc; cc = cn; sc = sn;
        }
    }
    out[idx] = acc;
}

// ---------------- launch ----------------------------------------------------
extern "C" void kernel_launch(void* const* d_in, const int* in_sizes, int n_in,
                              void* d_out, int out_size) {
    const float* features = (const float*)d_in[0];
    const int*   ei       = (const int*)d_in[1];
    const int*   batch    = (const int*)d_in[2];
    const float* W_embed  = (const float*)d_in[3];
    const float* W_mp     = (const float*)d_in[4];
    const float* W_read   = (const float*)d_in[5];
    float*       out      = (float*)d_out;

    const int n = in_sizes[0] / INF;
    const int E = in_sizes[1] / 2;

    float *p_bufA, *p_bufB, *p_dinv, *p_pool, *p_cnt, *p_y;
    float *p_wte, *p_wtm, *p_wtr;
    int   *p_deg, *p_offs, *p_cursor, *p_esrc;
    cudaGetSymbolAddress((void**)&p_bufA,   g_bufA);
    cudaGetSymbolAddress((void**)&p_bufB,   g_bufB);
    cudaGetSymbolAddress((void**)&p_dinv,   g_dinv);
    cudaGetSymbolAddress((void**)&p_deg,    g_deg);
    cudaGetSymbolAddress((void**)&p_offs,   g_offs);
    cudaGetSymbolAddress((void**)&p_cursor, g_cursor);
    cudaGetSymbolAddress((void**)&p_esrc,   g_esrc);
    cudaGetSymbolAddress((void**)&p_wte,    g_wt_embed);
    cudaGetSymbolAddress((void**)&p_wtm,    g_wt_mp);
    cudaGetSymbolAddress((void**)&p_wtr,    g_wt_read);
    cudaGetSymbolAddress((void**)&p_pool,   g_pool);
    cudaGetSymbolAddress((void**)&p_cnt,    g_cnt);
    cudaGetSymbolAddress((void**)&p_y,      g_y);

    const int gblocks = (n + 127) / 128;
    const int wtot_mp = HID * 16 * HID;     // 2048 * 128

    // -- embedding path --
    transpose_w<<<(INF * 16 * HID + 255) / 256, 256>>>(W_embed, p_wte, HID, INF);
    kan_gemm<INF><<<gblocks, 256>>>(features, p_wte, p_bufA, n);

    transpose_w<<<(wtot_mp + 255) / 256, 256>>>(W_mp, p_wtm, HID, HID);
    kan_gemm<HID><<<gblocks, 256>>>(p_bufA, p_wtm, p_bufB, n);

    // -- CSR build --
    cudaMemsetAsync(p_deg, 0, (size_t)n * sizeof(int));
    deg_kernel<<<(E + 255) / 256, 256>>>(ei, p_deg, E);
    scan_kernel<<<1, 1024>>>(p_deg, p_offs, p_cursor, n);
    dinv_kernel<<<(n + 255) / 256, 256>>>(p_deg, p_dinv, n);
    place_kernel<<<(E + 255) / 256, 256>>>(ei, p_cursor, p_esrc, E);

    // layer 0 aggregation
    gather_kernel<<<(n * 32 + 255) / 256, 256>>>(p_bufB, p_bufA, p_esrc, p_offs, p_dinv, n);

    // layers 1..2
    for (int l = 1; l < NLAY; l++) {
        transpose_w<<<(wtot_mp + 255) / 256, 256>>>(W_mp + (size_t)l * wtot_mp,
                                                    p_wtm + (size_t)l * wtot_mp, HID, HID);
        kan_gemm<HID><<<gblocks, 256>>>(p_bufA, p_wtm + (size_t)l * wtot_mp, p_bufB, n);
        gather_kernel<<<(n * 32 + 255) / 256, 256>>>(p_bufB, p_bufA, p_esrc, p_offs, p_dinv, n);
    }

    // -- mean pool + readout --
    transpose_w<<<(2 * LAT * HID * HARM + 255) / 256, 256>>>(W_read, p_wtr, LAT, HID);
    cudaMemsetAsync(p_pool, 0, NG * HID * sizeof(float));
    cudaMemsetAsync(p_cnt,  0, NG * sizeof(float));
    pool_kernel<<<(n + 255) / 256, 128>>>(p_bufA, batch, p_pool, p_cnt, n);
    mean_kernel<<<(NG * HID + 255) / 256, 256>>>(p_pool, p_cnt, p_y);
    kan_read_kernel<<<(NG * LAT + 255) / 256, 256>>>(p_y, p_wtr, out);
}